// round 2
// baseline (speedup 1.0000x reference)
#include <cuda_runtime.h>

#define NPTS 131072
#define NSEG 32

// ---------------- device scratch (statics: allocation-free rule) ----------------
__device__ float    g_bufA[(size_t)NPTS * 128 * 3];
__device__ float    g_bufB[(size_t)NPTS * 128 * 3];
__device__ float    g_bufC[(size_t)NPTS * 256 * 3];
__device__ float    g_bufD[(size_t)NPTS * 256 * 3];
__device__ unsigned g_dotbuf[(size_t)NPTS * 256];
__device__ unsigned g_segmax[NSEG * 256];
__device__ int      g_argmin[NSEG * 256];
__device__ float    g_pool1[NSEG * 128 * 3];

// monotone float -> uint map (order-preserving)
__device__ __forceinline__ unsigned f2u(float f) {
    unsigned b = __float_as_uint(f);
    return (b & 0x80000000u) ? ~b : (b | 0x80000000u);
}

// ---------------------------------------------------------------------------
// vn_gemm: out[n,o,i] = lrelu( Wf x , Wd x )   (LRELU=1)  or  Wf x (LRELU=0)
// x: [N, C, 3] row-major (or pos_emd + per-segment broadcast if CONCAT)
// Block: 16 points x 128 out-channels. 256 threads: warp w -> points {w, w+8},
// lane -> o in {lane, lane+32, lane+64, lane+96} (+ blockIdx.y*128 offset).
// ---------------------------------------------------------------------------
template <int C, int LRELU, int CONCAT>
__global__ __launch_bounds__(256)
void vn_gemm(const float* __restrict__ x, const float* __restrict__ x2,
             const int* __restrict__ ids,
             const float* __restrict__ Wf, const float* __restrict__ Wd,
             float* __restrict__ out, int Ot)
{
    __shared__ float Wfs[32][129];
    __shared__ float Wds[32][129];
    __shared__ float xs[3][32][17];

    const int tid  = threadIdx.x;
    const int lane = tid & 31;
    const int warp = tid >> 5;
    const int n0   = blockIdx.x * 16;
    const int o_off = blockIdx.y * 128;

    float af[2][4][3];
    float ad[2][4][3];
#pragma unroll
    for (int pt = 0; pt < 2; ++pt)
#pragma unroll
        for (int k = 0; k < 4; ++k)
#pragma unroll
            for (int i = 0; i < 3; ++i) { af[pt][k][i] = 0.f; ad[pt][k][i] = 0.f; }

    for (int c0 = 0; c0 < C; c0 += 32) {
        // weight tiles, transposed into smem (conflict-free: row stride 129)
#pragma unroll
        for (int r = 0; r < 16; ++r) {
            int idx = r * 256 + tid;
            int o = idx >> 5, j = idx & 31;
            Wfs[j][o] = Wf[(size_t)(o_off + o) * C + c0 + j];
            if (LRELU) Wds[j][o] = Wd[(size_t)(o_off + o) * C + c0 + j];
        }
        // x tile: 32 c x 16 p x 3 i
#pragma unroll
        for (int r = 0; r < 6; ++r) {
            int idx = r * 256 + tid;
            int j = idx & 31;
            int t = idx >> 5;   // 0..47
            int p = t & 15;
            int i = t >> 4;
            int c = c0 + j;
            int n = n0 + p;
            float v;
            if (!CONCAT) {
                v = x[(size_t)n * (C * 3) + c * 3 + i];
            } else {
                v = (c < 128) ? x[(size_t)n * 384 + c * 3 + i]
                              : x2[(size_t)ids[n] * 384 + (c - 128) * 3 + i];
            }
            xs[i][j][p] = v;
        }
        __syncthreads();

#pragma unroll 4
        for (int j = 0; j < 32; ++j) {
            float xv[2][3];
#pragma unroll
            for (int pt = 0; pt < 2; ++pt) {
                int p = warp + pt * 8;
                xv[pt][0] = xs[0][j][p];
                xv[pt][1] = xs[1][j][p];
                xv[pt][2] = xs[2][j][p];
            }
#pragma unroll
            for (int k = 0; k < 4; ++k) {
                float wf = Wfs[j][lane + 32 * k];
                float wd = 0.f;
                if (LRELU) wd = Wds[j][lane + 32 * k];
#pragma unroll
                for (int pt = 0; pt < 2; ++pt) {
                    af[pt][k][0] += wf * xv[pt][0];
                    af[pt][k][1] += wf * xv[pt][1];
                    af[pt][k][2] += wf * xv[pt][2];
                    if (LRELU) {
                        ad[pt][k][0] += wd * xv[pt][0];
                        ad[pt][k][1] += wd * xv[pt][1];
                        ad[pt][k][2] += wd * xv[pt][2];
                    }
                }
            }
        }
        __syncthreads();
    }

    // epilogue: VN leaky-relu (negative_slope = 0) + store
#pragma unroll
    for (int pt = 0; pt < 2; ++pt) {
        int n = n0 + warp + pt * 8;
#pragma unroll
        for (int k = 0; k < 4; ++k) {
            int o = o_off + lane + 32 * k;
            float p0 = af[pt][k][0], p1 = af[pt][k][1], p2 = af[pt][k][2];
            if (LRELU) {
                float d0 = ad[pt][k][0], d1 = ad[pt][k][1], d2 = ad[pt][k][2];
                float dot = p0 * d0 + p1 * d1 + p2 * d2;
                if (dot < 0.f) {
                    float s = dot / (d0 * d0 + d1 * d1 + d2 * d2 + 1e-7f);
                    p0 -= s * d0; p1 -= s * d1; p2 -= s * d2;
                }
            }
            size_t base = (size_t)n * Ot * 3 + (size_t)o * 3;
            out[base + 0] = p0;
            out[base + 1] = p1;
            out[base + 2] = p2;
        }
    }
}

// ---------------------------------------------------------------------------
// vn_dot: d = Wd x ; dot[n,c] = sum_i x[n,c,i]*d[n,c,i]
// stores encoded dot in g_dotbuf and block-reduced atomicMax into g_segmax.
// All 16 points of a block are in the same segment (16 | 4096).
// ---------------------------------------------------------------------------
template <int C>
__global__ __launch_bounds__(256)
void vn_dot(const float* __restrict__ x, const int* __restrict__ ids,
            const float* __restrict__ Wd)
{
    __shared__ float Wds[32][129];
    __shared__ float xs[3][32][17];
    __shared__ unsigned red[128];

    const int tid  = threadIdx.x;
    const int lane = tid & 31;
    const int warp = tid >> 5;
    const int n0   = blockIdx.x * 16;
    const int o_off = blockIdx.y * 128;

    float ad[2][4][3];
#pragma unroll
    for (int pt = 0; pt < 2; ++pt)
#pragma unroll
        for (int k = 0; k < 4; ++k)
#pragma unroll
            for (int i = 0; i < 3; ++i) ad[pt][k][i] = 0.f;

    for (int c0 = 0; c0 < C; c0 += 32) {
#pragma unroll
        for (int r = 0; r < 16; ++r) {
            int idx = r * 256 + tid;
            int o = idx >> 5, j = idx & 31;
            Wds[j][o] = Wd[(size_t)(o_off + o) * C + c0 + j];
        }
#pragma unroll
        for (int r = 0; r < 6; ++r) {
            int idx = r * 256 + tid;
            int j = idx & 31;
            int t = idx >> 5;
            int p = t & 15;
            int i = t >> 4;
            xs[i][j][p] = x[(size_t)(n0 + p) * (C * 3) + (c0 + j) * 3 + i];
        }
        __syncthreads();

#pragma unroll 4
        for (int j = 0; j < 32; ++j) {
            float xv[2][3];
#pragma unroll
            for (int pt = 0; pt < 2; ++pt) {
                int p = warp + pt * 8;
                xv[pt][0] = xs[0][j][p];
                xv[pt][1] = xs[1][j][p];
                xv[pt][2] = xs[2][j][p];
            }
#pragma unroll
            for (int k = 0; k < 4; ++k) {
                float wd = Wds[j][lane + 32 * k];
#pragma unroll
                for (int pt = 0; pt < 2; ++pt) {
                    ad[pt][k][0] += wd * xv[pt][0];
                    ad[pt][k][1] += wd * xv[pt][1];
                    ad[pt][k][2] += wd * xv[pt][2];
                }
            }
        }
        __syncthreads();
    }

    // init block reduction buffer
    for (int i = tid; i < 128; i += 256) red[i] = 0u;
    __syncthreads();

    const int s = ids[n0];
    unsigned um[4];
#pragma unroll
    for (int k = 0; k < 4; ++k) um[k] = 0u;

#pragma unroll
    for (int pt = 0; pt < 2; ++pt) {
        int n = n0 + warp + pt * 8;
#pragma unroll
        for (int k = 0; k < 4; ++k) {
            int o = o_off + lane + 32 * k;
            size_t xb = (size_t)n * C * 3 + (size_t)o * 3;
            float x0 = x[xb], x1 = x[xb + 1], x2 = x[xb + 2];
            float dotv = x0 * ad[pt][k][0] + x1 * ad[pt][k][1] + x2 * ad[pt][k][2];
            unsigned u = f2u(dotv);
            g_dotbuf[(size_t)n * C + o] = u;
            if (u > um[k]) um[k] = u;
        }
    }
#pragma unroll
    for (int k = 0; k < 4; ++k) atomicMax(&red[lane + 32 * k], um[k]);
    __syncthreads();
    for (int i = tid; i < 128; i += 256)
        atomicMax(&g_segmax[s * C + o_off + i], red[i]);
}

// ---------------------------------------------------------------------------
template <int C>
__global__ __launch_bounds__(256)
void seg_argmin(const int* __restrict__ ids)
{
    size_t idx = (size_t)blockIdx.x * 256 + threadIdx.x;   // over N*C, c fast
    int c = (int)(idx & (C - 1));
    int n = (int)(idx >> (C == 128 ? 7 : 8));
    unsigned u = g_dotbuf[idx];
    int s = ids[n];
    if (u == g_segmax[s * C + c]) atomicMin(&g_argmin[s * C + c], n);
}

__global__ void seg_init()
{
    int i = blockIdx.x * 256 + threadIdx.x;
    if (i < NSEG * 256) { g_segmax[i] = 0u; g_argmin[i] = 0x7fffffff; }
}

// ---------------------------------------------------------------------------
// gather winners per (segment, channel) + VNLeakyReLU (ns = 0)
// ---------------------------------------------------------------------------
template <int C>
__global__ __launch_bounds__(128)
void pool_relu(const float* __restrict__ xsrc, const float* __restrict__ Wr,
               float* __restrict__ outp)
{
    const int s = blockIdx.x;
    const int tid = threadIdx.x;
    __shared__ float ps[C][3];

    for (int c = tid; c < C; c += 128) {
        int n = g_argmin[s * C + c];
        size_t b = (size_t)n * C * 3 + (size_t)c * 3;
        ps[c][0] = xsrc[b];
        ps[c][1] = xsrc[b + 1];
        ps[c][2] = xsrc[b + 2];
    }
    __syncthreads();

    for (int c = tid; c < C; c += 128) {
        float d0 = 0.f, d1 = 0.f, d2 = 0.f;
        for (int k = 0; k < C; ++k) {
            float w = Wr[(size_t)c * C + k];
            d0 += w * ps[k][0];
            d1 += w * ps[k][1];
            d2 += w * ps[k][2];
        }
        float x0 = ps[c][0], x1 = ps[c][1], x2 = ps[c][2];
        float dot = x0 * d0 + x1 * d1 + x2 * d2;
        float o0 = x0, o1 = x1, o2 = x2;
        if (dot < 0.f) {
            float t = dot / (d0 * d0 + d1 * d1 + d2 * d2 + 1e-7f);
            o0 -= t * d0; o1 -= t * d1; o2 -= t * d2;
        }
        size_t b = ((size_t)s * C + c) * 3;
        outp[b + 0] = o0;
        outp[b + 1] = o1;
        outp[b + 2] = o2;
    }
}

// ---------------------------------------------------------------------------
extern "C" void kernel_launch(void* const* d_in, const int* in_sizes, int n_in,
                              void* d_out, int out_size)
{
    const float* pos = (const float*)d_in[0];
    const int*   ids = (const int*)d_in[1];
    const float* W1f = (const float*)d_in[2];
    const float* W1d = (const float*)d_in[3];
    const float* W2f = (const float*)d_in[4];
    const float* W2d = (const float*)d_in[5];
    const float* W3  = (const float*)d_in[6];
    const float* Wd1 = (const float*)d_in[7];
    const float* Wr3 = (const float*)d_in[8];
    const float* W4f = (const float*)d_in[9];
    const float* W4d = (const float*)d_in[10];
    const float* W5  = (const float*)d_in[11];
    const float* Wd2 = (const float*)d_in[12];
    const float* Wr5 = (const float*)d_in[13];
    float* out = (float*)d_out;

    float *bufA, *bufB, *bufC, *bufD, *pool1;
    cudaGetSymbolAddress((void**)&bufA, g_bufA);
    cudaGetSymbolAddress((void**)&bufB, g_bufB);
    cudaGetSymbolAddress((void**)&bufC, g_bufC);
    cudaGetSymbolAddress((void**)&bufD, g_bufD);
    cudaGetSymbolAddress((void**)&pool1, g_pool1);

    dim3 g1(NPTS / 16, 1);
    dim3 g2(NPTS / 16, 2);

    // stage 1: vn1 -> vn2 -> vn3
    vn_gemm<128, 1, 0><<<g1, 256>>>(pos,  nullptr, ids, W1f, W1d, bufA, 128);
    vn_gemm<128, 1, 0><<<g1, 256>>>(bufA, nullptr, ids, W2f, W2d, bufB, 128);
    vn_gemm<128, 0, 0><<<g1, 256>>>(bufB, nullptr, ids, W3,  nullptr, bufA, 128);

    // segment max-pool 1 + relu3
    seg_init<<<32, 256>>>();
    vn_dot<128><<<g1, 256>>>(bufA, ids, Wd1);
    seg_argmin<128><<<(NPTS * 128) / 256, 256>>>(ids);
    pool_relu<128><<<32, 128>>>(bufA, Wr3, pool1);

    // stage 2: concat(pos, broadcast pool1) -> vn4 -> vn5
    vn_gemm<256, 1, 1><<<g2, 256>>>(pos,  pool1, ids, W4f, W4d, bufC, 256);
    vn_gemm<256, 0, 0><<<g2, 256>>>(bufC, nullptr, ids, W5, nullptr, bufD, 256);

    // segment max-pool 2 + relu5 -> output [32, 256, 3]
    seg_init<<<32, 256>>>();
    vn_dot<256><<<g2, 256>>>(bufD, ids, Wd2);
    seg_argmin<256><<<(NPTS * 256) / 256, 256>>>(ids);
    pool_relu<256><<<32, 128>>>(bufD, Wr5, out);
}